// round 1
// baseline (speedup 1.0000x reference)
#include <cuda_runtime.h>

// Problem constants
#define Bb 8
#define Nn 2048
#define Mm 2048
#define Cc 768
#define Hh 12
#define Pp 4
#define Dd 64
// derived
#define ROWS (Bb * Nn)        // 16384 rows for both big GEMMs
#define GRP  (Bb * Hh)        // 96 groups
#define IMG_GRP_ELEMS (Mm * Dd)  // 131072 floats per group

// ---------------- device scratch (allocation-free rule) ----------------
__device__ float g_qp[ROWS * Cc];          // 48 MB  qp[b*N+n][c]
__device__ float g_imgT[GRP * IMG_GRP_ELEMS]; // 48 MB  imgT[g][m][d] (d contiguous)
__device__ float g_offx[ROWS * Pp];        // off x-coords per (b,n,p)
__device__ float g_logits[GRP * Nn];       // logits -> attn in place
__device__ float g_vspart[Bb * 16 * Cc];   // deterministic 2-stage v-sum
__device__ float g_vs[Bb * Cc];
__device__ float g_pv[Bb * Hh * Cc];       // pv[b][h][c]

// ---------------- SGEMM: [16384,768] x [768,768], fp32 ----------------
// MODE 0: plain row-major store into g_qp
// MODE 1: scatter into imgT layout (kp raw-reshape permutation)
#define BM 128
#define BN 128
#define BK 8
#define TM 8
#define TN 8

template <int MODE>
__global__ void __launch_bounds__(256) sgemm_kernel(const float* __restrict__ A,
                                                    const float* __restrict__ W)
{
    __shared__ float As[BK][BM];
    __shared__ float Bs[BK][BN];

    const int tid = threadIdx.x;
    const int blockRow = blockIdx.y * BM;
    const int blockCol = blockIdx.x * BN;

    const int aRow = tid >> 1;           // 0..127
    const int aCol = (tid & 1) << 2;     // 0 or 4
    const int bRow = tid >> 5;           // 0..7
    const int bCol = (tid & 31) << 2;    // 0..124

    const int tRow = (tid >> 4) * TM;    // 0..120
    const int tCol = (tid & 15) * TN;    // 0..120

    float acc[TM][TN];
#pragma unroll
    for (int i = 0; i < TM; i++)
#pragma unroll
        for (int j = 0; j < TN; j++) acc[i][j] = 0.0f;

    for (int k0 = 0; k0 < Cc; k0 += BK) {
        float4 a4 = *(const float4*)(A + (size_t)(blockRow + aRow) * Cc + k0 + aCol);
        As[aCol + 0][aRow] = a4.x;
        As[aCol + 1][aRow] = a4.y;
        As[aCol + 2][aRow] = a4.z;
        As[aCol + 3][aRow] = a4.w;
        *(float4*)(&Bs[bRow][bCol]) =
            *(const float4*)(W + (size_t)(k0 + bRow) * Cc + blockCol + bCol);
        __syncthreads();

#pragma unroll
        for (int kk = 0; kk < BK; kk++) {
            float ra[TM], rb[TN];
            float4 ra0 = *(const float4*)(&As[kk][tRow]);
            float4 ra1 = *(const float4*)(&As[kk][tRow + 4]);
            ra[0]=ra0.x; ra[1]=ra0.y; ra[2]=ra0.z; ra[3]=ra0.w;
            ra[4]=ra1.x; ra[5]=ra1.y; ra[6]=ra1.z; ra[7]=ra1.w;
            float4 rb0 = *(const float4*)(&Bs[kk][tCol]);
            float4 rb1 = *(const float4*)(&Bs[kk][tCol + 4]);
            rb[0]=rb0.x; rb[1]=rb0.y; rb[2]=rb0.z; rb[3]=rb0.w;
            rb[4]=rb1.x; rb[5]=rb1.y; rb[6]=rb1.z; rb[7]=rb1.w;
#pragma unroll
            for (int i = 0; i < TM; i++)
#pragma unroll
                for (int j = 0; j < TN; j++)
                    acc[i][j] = fmaf(ra[i], rb[j], acc[i][j]);
        }
        __syncthreads();
    }

    if (MODE == 0) {
#pragma unroll
        for (int i = 0; i < TM; i++) {
            const int r = blockRow + tRow + i;
            float4 v0 = make_float4(acc[i][0], acc[i][1], acc[i][2], acc[i][3]);
            float4 v1 = make_float4(acc[i][4], acc[i][5], acc[i][6], acc[i][7]);
            *(float4*)(g_qp + (size_t)r * Cc + blockCol + tCol) = v0;
            *(float4*)(g_qp + (size_t)r * Cc + blockCol + tCol + 4) = v1;
        }
    } else {
        // kp element (row r = b*2048+mm, col cc = h*64+dd) goes to
        // imgT[g=b*12+h][ (mm*64+dd) & 2047 ][ (mm*64+dd) >> 11 ]
#pragma unroll
        for (int i = 0; i < TM; i++) {
            const int r = blockRow + tRow + i;
            const int b = r >> 11;
            const int mm = r & 2047;
#pragma unroll
            for (int j = 0; j < TN; j++) {
                const int cc = blockCol + tCol + j;
                const int h = cc >> 6;
                const int dd = cc & 63;
                const int g = b * Hh + h;
                const int t = mm * Dd + dd;
                g_imgT[(size_t)g * IMG_GRP_ELEMS + (size_t)(t & (Mm - 1)) * Dd + (t >> 11)] =
                    acc[i][j];
            }
        }
    }
}

// ---------------- offsets: offx[b,n,p] = q[b,n,:] . offW[:,2p] + offb[2p] ----
__global__ void __launch_bounds__(256) off_kernel(const float* __restrict__ q,
                                                  const float* __restrict__ offW,
                                                  const float* __restrict__ offb)
{
    const int gwarp = (blockIdx.x * blockDim.x + threadIdx.x) >> 5;  // 0..16383
    const int lane = threadIdx.x & 31;
    const float* qrow = q + (size_t)gwarp * Cc;
    float a0 = 0.f, a1 = 0.f, a2 = 0.f, a3 = 0.f;
    for (int c = lane; c < Cc; c += 32) {
        const float qv = qrow[c];
        const float* wr = offW + c * (2 * Pp);
        a0 = fmaf(qv, wr[0], a0);
        a1 = fmaf(qv, wr[2], a1);
        a2 = fmaf(qv, wr[4], a2);
        a3 = fmaf(qv, wr[6], a3);
    }
#pragma unroll
    for (int o = 16; o > 0; o >>= 1) {
        a0 += __shfl_xor_sync(0xffffffffu, a0, o);
        a1 += __shfl_xor_sync(0xffffffffu, a1, o);
        a2 += __shfl_xor_sync(0xffffffffu, a2, o);
        a3 += __shfl_xor_sync(0xffffffffu, a3, o);
    }
    if (lane == 0) {
        g_offx[gwarp * 4 + 0] = a0 + offb[0];
        g_offx[gwarp * 4 + 1] = a1 + offb[2];
        g_offx[gwarp * 4 + 2] = a2 + offb[4];
        g_offx[gwarp * 4 + 3] = a3 + offb[6];
    }
}

// ---------------- v column sums (deterministic 2-stage) ----------------
__global__ void __launch_bounds__(256) vspart_kernel(const float* __restrict__ v)
{
    const int idx = blockIdx.x * blockDim.x + threadIdx.x;  // 0..98303
    const int c = idx % Cc;
    const int chunk = (idx / Cc) & 15;
    const int b = idx / (Cc * 16);
    const float* p = v + ((size_t)b * Mm + (size_t)chunk * 128) * Cc + c;
    float s = 0.f;
#pragma unroll 4
    for (int m = 0; m < 128; m++) s += p[(size_t)m * Cc];
    g_vspart[idx] = s;
}

__global__ void __launch_bounds__(256) vsred_kernel()
{
    const int idx = blockIdx.x * blockDim.x + threadIdx.x;  // 0..6143
    const int c = idx % Cc;
    const int b = idx / Cc;
    float s = 0.f;
#pragma unroll
    for (int ch = 0; ch < 16; ch++) s += g_vspart[((size_t)b * 16 + ch) * Cc + c];
    g_vs[idx] = s;
}

// ---------------- pv[b,h,c'] = sum_d (vs[b]@vW)[h*64+d] * projW[h*64+d, c'] ---
__global__ void __launch_bounds__(256) pv_kernel(const float* __restrict__ vW,
                                                 const float* __restrict__ projW)
{
    __shared__ float vs_s[Cc];
    __shared__ float vsum_s[Cc];
    const int b = blockIdx.x;
    for (int i = threadIdx.x; i < Cc; i += 256) vs_s[i] = g_vs[b * Cc + i];
    __syncthreads();
    for (int o = threadIdx.x; o < Cc; o += 256) {
        float s = 0.f;
        for (int c = 0; c < Cc; c++) s = fmaf(vs_s[c], vW[(size_t)c * Cc + o], s);
        vsum_s[o] = s;
    }
    __syncthreads();
    for (int o = threadIdx.x; o < Hh * Cc; o += 256) {
        const int h = o / Cc;
        const int c = o % Cc;
        float s = 0.f;
#pragma unroll
        for (int d = 0; d < Dd; d++)
            s = fmaf(vsum_s[h * Dd + d], projW[(size_t)(h * Dd + d) * Cc + c], s);
        g_pv[(size_t)b * Hh * Cc + o] = s;
    }
}

// ---------------- sampling + dot: logits[b,h,n] ----------------
__global__ void __launch_bounds__(256) sample_kernel()
{
    const int gwarp = (blockIdx.x * blockDim.x + threadIdx.x) >> 5;  // 0..196607
    const int lane = threadIdx.x & 31;
    const int g = gwarp >> 11;     // /2048
    const int n2 = gwarp & 2047;
    const int b = g / Hh;
    const int h = g % Hh;
    const int nq = (h * Nn + n2) / Hh;  // RAW-reshape index mixing

    const float* imgg = g_imgT + (size_t)g * IMG_GRP_ELEMS;
    float accx = 0.f, accy = 0.f;
#pragma unroll
    for (int p = 0; p < Pp; p++) {
        const float offx = g_offx[((size_t)b * Nn + nq) * Pp + p];
        // replicate the reference's grid round trip in fp32
        const float gx = offx / 2047.0f * 2.0f - 1.0f;
        const float x = (gx + 1.0f) * 0.5f * 2047.0f;
        const float x0f = floorf(x);
        const float w = x - x0f;
        const int x0 = (int)x0f;
        const int x1 = x0 + 1;
        const float w0 = (x0 >= 0 && x0 < Mm) ? (1.0f - w) : 0.0f;
        const float w1 = (x1 >= 0 && x1 < Mm) ? w : 0.0f;
        const int x0c = min(max(x0, 0), Mm - 1);
        const int x1c = min(max(x1, 0), Mm - 1);
        const float2 v0 = *(const float2*)(imgg + (size_t)x0c * Dd + 2 * lane);
        const float2 v1 = *(const float2*)(imgg + (size_t)x1c * Dd + 2 * lane);
        accx += w0 * v0.x + w1 * v1.x;
        accy += w0 * v0.y + w1 * v1.y;
    }
    const float2 qv =
        *(const float2*)(g_qp + ((size_t)b * Nn + n2) * Cc + h * Dd + 2 * lane);
    float partial = accx * qv.x + accy * qv.y;
#pragma unroll
    for (int o = 16; o > 0; o >>= 1) partial += __shfl_xor_sync(0xffffffffu, partial, o);
    if (lane == 0) g_logits[gwarp] = partial * (0.125f * 0.25f);  // scale/P
}

// ---------------- softmax over N per (b,h) ----------------
__global__ void __launch_bounds__(256) softmax_kernel()
{
    __shared__ float red[256];
    const int row = blockIdx.x;  // 0..95
    float* ptr = g_logits + (size_t)row * Nn;
    const int tid = threadIdx.x;
    float vals[8];
    float m = -1e30f;
#pragma unroll
    for (int i = 0; i < 8; i++) {
        vals[i] = ptr[tid + i * 256];
        m = fmaxf(m, vals[i]);
    }
    red[tid] = m;
    __syncthreads();
    for (int s = 128; s > 0; s >>= 1) {
        if (tid < s) red[tid] = fmaxf(red[tid], red[tid + s]);
        __syncthreads();
    }
    m = red[0];
    __syncthreads();
    float sum = 0.f;
#pragma unroll
    for (int i = 0; i < 8; i++) {
        vals[i] = expf(vals[i] - m);
        sum += vals[i];
    }
    red[tid] = sum;
    __syncthreads();
    for (int s = 128; s > 0; s >>= 1) {
        if (tid < s) red[tid] += red[tid + s];
        __syncthreads();
    }
    const float inv = 1.0f / red[0];
#pragma unroll
    for (int i = 0; i < 8; i++) ptr[tid + i * 256] = vals[i] * inv;
}

// ---------------- output: out[b,n,:] = attn[b,:,n] @ pv[b] + projb ----------
#define OUT_ROWS 32
__global__ void __launch_bounds__(256) out_kernel(const float* __restrict__ projb,
                                                  float* __restrict__ out)
{
    __shared__ float pv_s[Hh * Cc];
    __shared__ float a_s[Hh];
    const int b = blockIdx.y;
    const int n0 = blockIdx.x * OUT_ROWS;
    const int tid = threadIdx.x;
    for (int i = tid; i < Hh * Cc; i += 256) pv_s[i] = g_pv[(size_t)b * Hh * Cc + i];
    __syncthreads();
    for (int n = n0; n < n0 + OUT_ROWS; n++) {
        __syncthreads();
        if (tid < Hh) a_s[tid] = g_logits[((size_t)b * Hh + tid) * Nn + n];
        __syncthreads();
        for (int c = tid; c < Cc; c += 256) {
            float s = projb[c];
#pragma unroll
            for (int h = 0; h < Hh; h++) s = fmaf(a_s[h], pv_s[h * Cc + c], s);
            out[((size_t)b * Nn + n) * Cc + c] = s;
        }
    }
}

// ---------------- launch ----------------
extern "C" void kernel_launch(void* const* d_in, const int* in_sizes, int n_in,
                              void* d_out, int out_size)
{
    (void)in_sizes; (void)n_in; (void)out_size;
    const float* q     = (const float*)d_in[0];
    const float* k     = (const float*)d_in[1];
    const float* v     = (const float*)d_in[2];
    const float* qW    = (const float*)d_in[3];
    const float* kW    = (const float*)d_in[4];
    const float* vW    = (const float*)d_in[5];
    const float* offW  = (const float*)d_in[6];
    const float* offb  = (const float*)d_in[7];
    const float* projW = (const float*)d_in[8];
    const float* projb = (const float*)d_in[9];
    float* out = (float*)d_out;

    dim3 gemm_grid(Cc / BN, ROWS / BM);  // (6, 128)
    sgemm_kernel<0><<<gemm_grid, 256>>>(q, qW);   // qp
    sgemm_kernel<1><<<gemm_grid, 256>>>(k, kW);   // kp -> imgT scatter
    off_kernel<<<ROWS / 8, 256>>>(q, offW, offb); // 2048 blocks
    vspart_kernel<<<(Bb * 16 * Cc) / 256, 256>>>(v);
    vsred_kernel<<<(Bb * Cc) / 256, 256>>>();
    sample_kernel<<<(GRP * Nn) / 8, 256>>>();     // 24576 blocks, 1 warp per (g,n)
    softmax_kernel<<<GRP, 256>>>();
    pv_kernel<<<Bb, 256>>>(vW, projW);
    out_kernel<<<dim3(Nn / OUT_ROWS, Bb), 256>>>(projb, out);
}

// round 2
// speedup vs baseline: 2.0605x; 2.0605x over previous
#include <cuda_runtime.h>
#include <cuda_bf16.h>
#include <cstdint>

// Problem constants
#define Bb 8
#define Nn 2048
#define Mm 2048
#define Cc 768
#define Hh 12
#define Pp 4
#define Dd 64
#define ROWS (Bb * Nn)        // 16384
#define GRP  (Bb * Hh)        // 96
#define IMG_GRP_ELEMS (Mm * Dd)

// ---------------- device scratch ----------------
__device__ float g_qp[ROWS * Cc];
__device__ float g_imgT[GRP * IMG_GRP_ELEMS];
__device__ float g_offx[ROWS * Pp];
__device__ float g_logits[GRP * Nn];
__device__ float g_vspart[Bb * 16 * Cc];
__device__ float g_vs[Bb * Cc];
__device__ float g_pv[Bb * Hh * Cc];

// ================= bf16 split-2 tensor-core GEMM =================
// C[16384,768] = A[16384,768] * W[768,768], fp32 in/out.
// A = Ah + Al (bf16), W = Wh + Wl (bf16); C ~= Ah*Wh + Ah*Wl + Al*Wh.
#define BM 128
#define BN 128
#define BKF 32           // fp32 k per iter
#define A_U32S 20        // A smem row stride in u32 (40 bf16 = 80B)
#define B_U32S 68        // B smem row stride in u32 (136 bf16 = 272B)

__device__ __forceinline__ uint32_t f2bf2(float x, float y) {
    __nv_bfloat162 t = __floats2bfloat162_rn(x, y);
    return *reinterpret_cast<uint32_t*>(&t);
}
__device__ __forceinline__ float bfres(float x) {
    // residual after bf16 rounding
    return x - __bfloat162float(__float2bfloat16_rn(x));
}

__device__ __forceinline__ void ldm_x4(uint32_t* r, uint32_t addr) {
    asm volatile("ldmatrix.sync.aligned.m8n8.x4.shared.b16 {%0,%1,%2,%3}, [%4];"
                 : "=r"(r[0]), "=r"(r[1]), "=r"(r[2]), "=r"(r[3]) : "r"(addr));
}
__device__ __forceinline__ void ldm_x4t(uint32_t* r, uint32_t addr) {
    asm volatile("ldmatrix.sync.aligned.m8n8.x4.trans.shared.b16 {%0,%1,%2,%3}, [%4];"
                 : "=r"(r[0]), "=r"(r[1]), "=r"(r[2]), "=r"(r[3]) : "r"(addr));
}
__device__ __forceinline__ void mma16816(float* c, const uint32_t* a, const uint32_t* b) {
    asm volatile(
        "mma.sync.aligned.m16n8k16.row.col.f32.bf16.bf16.f32 "
        "{%0,%1,%2,%3}, {%4,%5,%6,%7}, {%8,%9}, {%0,%1,%2,%3};"
        : "+f"(c[0]), "+f"(c[1]), "+f"(c[2]), "+f"(c[3])
        : "r"(a[0]), "r"(a[1]), "r"(a[2]), "r"(a[3]), "r"(b[0]), "r"(b[1]));
}

// MODE 0: store to g_qp; MODE 1: imgT scatter (kp raw-reshape permutation)
template <int MODE>
__global__ void __launch_bounds__(256) tgemm_kernel(const float* __restrict__ A,
                                                    const float* __restrict__ W)
{
    __shared__ uint32_t sAh[BM * A_U32S], sAl[BM * A_U32S];
    __shared__ uint32_t sBh[BKF * B_U32S], sBl[BKF * B_U32S];

    const int tid  = threadIdx.x;
    const int lane = tid & 31;
    const int warp = tid >> 5;
    const int wm = warp >> 1;          // 0..3  (32 rows each)
    const int wn = warp & 1;           // 0..1  (64 cols each)
    const int blockRow = blockIdx.y * BM;
    const int blockCol = blockIdx.x * BN;

    // gmem load coords
    const int am = tid >> 3;           // 0..31 (+32*pass)
    const int aq = (tid & 7) << 2;     // k offset 0..28
    const int bk = tid >> 5;           // 0..7 (+8*pass)
    const int bq = (tid & 31) << 2;    // n offset 0..124

    float acc[2][8][4];
#pragma unroll
    for (int i = 0; i < 2; i++)
#pragma unroll
        for (int j = 0; j < 8; j++)
#pragma unroll
            for (int t = 0; t < 4; t++) acc[i][j][t] = 0.0f;

    const uint32_t sAh_b = (uint32_t)__cvta_generic_to_shared(sAh);
    const uint32_t sAl_b = (uint32_t)__cvta_generic_to_shared(sAl);
    const uint32_t sBh_b = (uint32_t)__cvta_generic_to_shared(sBh);
    const uint32_t sBl_b = (uint32_t)__cvta_generic_to_shared(sBl);

    float4 pa[4], pb[4];
#pragma unroll
    for (int p = 0; p < 4; p++) {
        pa[p] = *(const float4*)(A + (size_t)(blockRow + am + p * 32) * Cc + aq);
        pb[p] = *(const float4*)(W + (size_t)(bk + p * 8) * Cc + blockCol + bq);
    }

    for (int it = 0; it < Cc / BKF; it++) {
        // STS with split
#pragma unroll
        for (int p = 0; p < 4; p++) {
            const int m = am + p * 32;
            const int ki = aq >> 1;  // u32 index
            sAh[m * A_U32S + ki]     = f2bf2(pa[p].x, pa[p].y);
            sAh[m * A_U32S + ki + 1] = f2bf2(pa[p].z, pa[p].w);
            sAl[m * A_U32S + ki]     = f2bf2(bfres(pa[p].x), bfres(pa[p].y));
            sAl[m * A_U32S + ki + 1] = f2bf2(bfres(pa[p].z), bfres(pa[p].w));
            const int kr = bk + p * 8;
            const int ni = bq >> 1;
            sBh[kr * B_U32S + ni]     = f2bf2(pb[p].x, pb[p].y);
            sBh[kr * B_U32S + ni + 1] = f2bf2(pb[p].z, pb[p].w);
            sBl[kr * B_U32S + ni]     = f2bf2(bfres(pb[p].x), bfres(pb[p].y));
            sBl[kr * B_U32S + ni + 1] = f2bf2(bfres(pb[p].z), bfres(pb[p].w));
        }
        __syncthreads();

        if (it + 1 < Cc / BKF) {
            const int k0 = (it + 1) * BKF;
#pragma unroll
            for (int p = 0; p < 4; p++) {
                pa[p] = *(const float4*)(A + (size_t)(blockRow + am + p * 32) * Cc + k0 + aq);
                pb[p] = *(const float4*)(W + (size_t)(k0 + bk + p * 8) * Cc + blockCol + bq);
            }
        }

        // compute: 2 k-steps of 16
#pragma unroll
        for (int ks = 0; ks < 2; ks++) {
            uint32_t ah[2][4], al[2][4], bh[4][4], bl[4][4];
#pragma unroll
            for (int mt = 0; mt < 2; mt++) {
                const int row = wm * 32 + mt * 16 + (lane & 15);
                const uint32_t off = row * (A_U32S * 4) + ks * 32 + ((lane >> 4) << 4);
                ldm_x4(ah[mt], sAh_b + off);
                ldm_x4(al[mt], sAl_b + off);
            }
#pragma unroll
            for (int np = 0; np < 4; np++) {
                const int kr = ks * 16 + (lane & 15);
                const uint32_t off = kr * (B_U32S * 4) + wn * 128 + np * 32 + ((lane >> 4) << 4);
                ldm_x4t(bh[np], sBh_b + off);
                ldm_x4t(bl[np], sBl_b + off);
            }
#pragma unroll
            for (int mt = 0; mt < 2; mt++)
#pragma unroll
                for (int j = 0; j < 8; j++) {
                    const int np = j >> 1;
                    const int hf = (j & 1) << 1;
                    mma16816(acc[mt][j], ah[mt], &bh[np][hf]);
                    mma16816(acc[mt][j], ah[mt], &bl[np][hf]);
                    mma16816(acc[mt][j], al[mt], &bh[np][hf]);
                }
        }
        __syncthreads();
    }

    // epilogue
#pragma unroll
    for (int mt = 0; mt < 2; mt++) {
        const int row0 = blockRow + wm * 32 + mt * 16 + (lane >> 2);
#pragma unroll
        for (int j = 0; j < 8; j++) {
            const int col = blockCol + wn * 64 + j * 8 + ((lane & 3) << 1);
            if (MODE == 0) {
                *(float2*)(g_qp + (size_t)row0 * Cc + col) =
                    make_float2(acc[mt][j][0], acc[mt][j][1]);
                *(float2*)(g_qp + (size_t)(row0 + 8) * Cc + col) =
                    make_float2(acc[mt][j][2], acc[mt][j][3]);
            } else {
#pragma unroll
                for (int e = 0; e < 4; e++) {
                    const int r = row0 + ((e >> 1) << 3);
                    const int cc = col + (e & 1);
                    const int b = r >> 11;
                    const int mm = r & 2047;
                    const int h = cc >> 6;
                    const int dd = cc & 63;
                    const int g = b * Hh + h;
                    const int t = mm * Dd + dd;
                    g_imgT[(size_t)g * IMG_GRP_ELEMS +
                           (size_t)(t & (Mm - 1)) * Dd + (t >> 11)] = acc[mt][j][e];
                }
            }
        }
    }
}

// ---------------- offsets ----------------
__global__ void __launch_bounds__(256) off_kernel(const float* __restrict__ q,
                                                  const float* __restrict__ offW,
                                                  const float* __restrict__ offb)
{
    const int gwarp = (blockIdx.x * blockDim.x + threadIdx.x) >> 5;
    const int lane = threadIdx.x & 31;
    const float* qrow = q + (size_t)gwarp * Cc;
    float a0 = 0.f, a1 = 0.f, a2 = 0.f, a3 = 0.f;
    for (int c = lane; c < Cc; c += 32) {
        const float qv = qrow[c];
        const float* wr = offW + c * (2 * Pp);
        a0 = fmaf(qv, wr[0], a0);
        a1 = fmaf(qv, wr[2], a1);
        a2 = fmaf(qv, wr[4], a2);
        a3 = fmaf(qv, wr[6], a3);
    }
#pragma unroll
    for (int o = 16; o > 0; o >>= 1) {
        a0 += __shfl_xor_sync(0xffffffffu, a0, o);
        a1 += __shfl_xor_sync(0xffffffffu, a1, o);
        a2 += __shfl_xor_sync(0xffffffffu, a2, o);
        a3 += __shfl_xor_sync(0xffffffffu, a3, o);
    }
    if (lane == 0) {
        g_offx[gwarp * 4 + 0] = a0 + offb[0];
        g_offx[gwarp * 4 + 1] = a1 + offb[2];
        g_offx[gwarp * 4 + 2] = a2 + offb[4];
        g_offx[gwarp * 4 + 3] = a3 + offb[6];
    }
}

// ---------------- v column sums (float4) ----------------
__global__ void __launch_bounds__(256) vspart_kernel(const float* __restrict__ v)
{
    const int idx = blockIdx.x * blockDim.x + threadIdx.x;  // 0..24575
    const int c4 = idx % (Cc / 4);
    const int chunk = (idx / (Cc / 4)) & 15;
    const int b = idx / ((Cc / 4) * 16);
    const float4* p = (const float4*)(v + ((size_t)b * Mm + (size_t)chunk * 128) * Cc) + c4;
    float4 s = make_float4(0.f, 0.f, 0.f, 0.f);
#pragma unroll 4
    for (int m = 0; m < 128; m++) {
        float4 t = p[(size_t)m * (Cc / 4)];
        s.x += t.x; s.y += t.y; s.z += t.z; s.w += t.w;
    }
    ((float4*)g_vspart)[idx] = s;
}

__global__ void __launch_bounds__(256) vsred_kernel()
{
    const int idx = blockIdx.x * blockDim.x + threadIdx.x;
    const int c = idx % Cc;
    const int b = idx / Cc;
    float s = 0.f;
#pragma unroll
    for (int ch = 0; ch < 16; ch++) s += g_vspart[((size_t)b * 16 + ch) * Cc + c];
    g_vs[idx] = s;
}

// ---------------- pv ----------------
__global__ void __launch_bounds__(256) pv_kernel(const float* __restrict__ vW,
                                                 const float* __restrict__ projW)
{
    __shared__ float vs_s[Cc];
    __shared__ float vsum_s[Cc];
    const int b = blockIdx.x;
    for (int i = threadIdx.x; i < Cc; i += 256) vs_s[i] = g_vs[b * Cc + i];
    __syncthreads();
    for (int o = threadIdx.x; o < Cc; o += 256) {
        float s = 0.f;
        for (int c = 0; c < Cc; c++) s = fmaf(vs_s[c], vW[(size_t)c * Cc + o], s);
        vsum_s[o] = s;
    }
    __syncthreads();
    for (int o = threadIdx.x; o < Hh * Cc; o += 256) {
        const int h = o / Cc;
        const int c = o % Cc;
        float s = 0.f;
#pragma unroll
        for (int d = 0; d < Dd; d++)
            s = fmaf(vsum_s[h * Dd + d], projW[(size_t)(h * Dd + d) * Cc + c], s);
        g_pv[(size_t)b * Hh * Cc + o] = s;
    }
}

// ---------------- sampling + dot ----------------
__global__ void __launch_bounds__(256) sample_kernel()
{
    const int gwarp = (blockIdx.x * blockDim.x + threadIdx.x) >> 5;
    const int lane = threadIdx.x & 31;
    const int g = gwarp >> 11;
    const int n2 = gwarp & 2047;
    const int b = g / Hh;
    const int h = g % Hh;
    const int nq = (h * Nn + n2) / Hh;

    const float* imgg = g_imgT + (size_t)g * IMG_GRP_ELEMS;
    float accx = 0.f, accy = 0.f;
#pragma unroll
    for (int p = 0; p < Pp; p++) {
        const float offx = g_offx[((size_t)b * Nn + nq) * Pp + p];
        const float gx = offx / 2047.0f * 2.0f - 1.0f;
        const float x = (gx + 1.0f) * 0.5f * 2047.0f;
        const float x0f = floorf(x);
        const float w = x - x0f;
        const int x0 = (int)x0f;
        const int x1 = x0 + 1;
        const float w0 = (x0 >= 0 && x0 < Mm) ? (1.0f - w) : 0.0f;
        const float w1 = (x1 >= 0 && x1 < Mm) ? w : 0.0f;
        const int x0c = min(max(x0, 0), Mm - 1);
        const int x1c = min(max(x1, 0), Mm - 1);
        const float2 v0 = *(const float2*)(imgg + (size_t)x0c * Dd + 2 * lane);
        const float2 v1 = *(const float2*)(imgg + (size_t)x1c * Dd + 2 * lane);
        accx += w0 * v0.x + w1 * v1.x;
        accy += w0 * v0.y + w1 * v1.y;
    }
    const float2 qv =
        *(const float2*)(g_qp + ((size_t)b * Nn + n2) * Cc + h * Dd + 2 * lane);
    float partial = accx * qv.x + accy * qv.y;
#pragma unroll
    for (int o = 16; o > 0; o >>= 1) partial += __shfl_xor_sync(0xffffffffu, partial, o);
    if (lane == 0) g_logits[gwarp] = partial * (0.125f * 0.25f);
}

// ---------------- softmax ----------------
__global__ void __launch_bounds__(256) softmax_kernel()
{
    __shared__ float red[256];
    const int row = blockIdx.x;
    float* ptr = g_logits + (size_t)row * Nn;
    const int tid = threadIdx.x;
    float vals[8];
    float m = -1e30f;
#pragma unroll
    for (int i = 0; i < 8; i++) {
        vals[i] = ptr[tid + i * 256];
        m = fmaxf(m, vals[i]);
    }
    red[tid] = m;
    __syncthreads();
    for (int s = 128; s > 0; s >>= 1) {
        if (tid < s) red[tid] = fmaxf(red[tid], red[tid + s]);
        __syncthreads();
    }
    m = red[0];
    __syncthreads();
    float sum = 0.f;
#pragma unroll
    for (int i = 0; i < 8; i++) {
        vals[i] = expf(vals[i] - m);
        sum += vals[i];
    }
    red[tid] = sum;
    __syncthreads();
    for (int s = 128; s > 0; s >>= 1) {
        if (tid < s) red[tid] += red[tid + s];
        __syncthreads();
    }
    const float inv = 1.0f / red[0];
#pragma unroll
    for (int i = 0; i < 8; i++) ptr[tid + i * 256] = vals[i] * inv;
}

// ---------------- output ----------------
#define OUT_ROWS 32
__global__ void __launch_bounds__(256) out_kernel(const float* __restrict__ projb,
                                                  float* __restrict__ out)
{
    __shared__ float pv_s[Hh * Cc];
    __shared__ float a_s[Hh];
    const int b = blockIdx.y;
    const int n0 = blockIdx.x * OUT_ROWS;
    const int tid = threadIdx.x;
    for (int i = tid; i < Hh * Cc; i += 256) pv_s[i] = g_pv[(size_t)b * Hh * Cc + i];
    __syncthreads();
    for (int n = n0; n < n0 + OUT_ROWS; n++) {
        __syncthreads();
        if (tid < Hh) a_s[tid] = g_logits[((size_t)b * Hh + tid) * Nn + n];
        __syncthreads();
        for (int c = tid; c < Cc; c += 256) {
            float s = projb[c];
#pragma unroll
            for (int h = 0; h < Hh; h++) s = fmaf(a_s[h], pv_s[h * Cc + c], s);
            out[((size_t)b * Nn + n) * Cc + c] = s;
        }
    }
}

// ---------------- launch ----------------
extern "C" void kernel_launch(void* const* d_in, const int* in_sizes, int n_in,
                              void* d_out, int out_size)
{
    (void)in_sizes; (void)n_in; (void)out_size;
    const float* q     = (const float*)d_in[0];
    const float* k     = (const float*)d_in[1];
    const float* v     = (const float*)d_in[2];
    const float* qW    = (const float*)d_in[3];
    const float* kW    = (const float*)d_in[4];
    const float* vW    = (const float*)d_in[5];
    const float* offW  = (const float*)d_in[6];
    const float* offb  = (const float*)d_in[7];
    const float* projW = (const float*)d_in[8];
    const float* projb = (const float*)d_in[9];
    float* out = (float*)d_out;

    dim3 gemm_grid(Cc / BN, ROWS / BM);  // (6, 128)
    tgemm_kernel<1><<<gemm_grid, 256>>>(k, kW);   // kp -> imgT
    tgemm_kernel<0><<<gemm_grid, 256>>>(q, qW);   // qp
    off_kernel<<<ROWS / 8, 256>>>(q, offW, offb);
    vspart_kernel<<<(Bb * 16 * (Cc / 4)) / 256, 256>>>(v);
    vsred_kernel<<<(Bb * Cc) / 256, 256>>>();
    sample_kernel<<<(GRP * Nn) / 8, 256>>>();
    softmax_kernel<<<GRP, 256>>>();
    pv_kernel<<<Bb, 256>>>(vW, projW);
    out_kernel<<<dim3(Nn / OUT_ROWS, Bb), 256>>>(projb, out);
}

// round 4
// speedup vs baseline: 2.0818x; 1.0103x over previous
#include <cuda_runtime.h>
#include <cuda_bf16.h>
#include <cstdint>

// Problem constants
#define Bb 8
#define Nn 2048
#define Mm 2048
#define Cc 768
#define Hh 12
#define Pp 4
#define Dd 64
#define ROWS (Bb * Nn)
#define GRP  (Bb * Hh)
#define IMG_GRP_ELEMS (Mm * Dd)

// ---------------- device scratch ----------------
__device__ float g_qp[ROWS * Cc];
__device__ float g_imgT[GRP * IMG_GRP_ELEMS];
__device__ float g_offx[ROWS * Pp];
__device__ float g_logits[GRP * Nn];
__device__ float g_vspart[Bb * 128 * Cc];
__device__ float g_vs[Bb * Cc];
__device__ float g_pv[Bb * Hh * Cc];
__device__ __nv_bfloat16 g_Ah[ROWS * Cc];     // activation hi
__device__ __nv_bfloat16 g_Al[ROWS * Cc];     // activation lo (residual)
__device__ __nv_bfloat16 g_Wh[2][Cc * Cc];    // weight hi  [k][n]
__device__ __nv_bfloat16 g_Wl[2][Cc * Cc];    // weight lo

// ================= helpers =================
__device__ __forceinline__ uint32_t smem_u32(const void* p) {
    uint32_t a;
    asm("{ .reg .u64 t; cvta.to.shared.u64 t, %1; cvt.u32.u64 %0, t; }"
        : "=r"(a) : "l"(p));
    return a;
}
__device__ __forceinline__ uint32_t f2bf2(float x, float y) {
    __nv_bfloat162 t = __floats2bfloat162_rn(x, y);
    return *reinterpret_cast<uint32_t*>(&t);
}
__device__ __forceinline__ float bfres(float x) {
    return x - __bfloat162float(__float2bfloat16_rn(x));
}
__device__ __forceinline__ void ldm_x4(uint32_t* r, uint32_t addr) {
    asm volatile("ldmatrix.sync.aligned.m8n8.x4.shared.b16 {%0,%1,%2,%3}, [%4];"
                 : "=r"(r[0]), "=r"(r[1]), "=r"(r[2]), "=r"(r[3]) : "r"(addr));
}
__device__ __forceinline__ void ldm_x4t(uint32_t* r, uint32_t addr) {
    asm volatile("ldmatrix.sync.aligned.m8n8.x4.trans.shared.b16 {%0,%1,%2,%3}, [%4];"
                 : "=r"(r[0]), "=r"(r[1]), "=r"(r[2]), "=r"(r[3]) : "r"(addr));
}
__device__ __forceinline__ void mma16816(float* c, const uint32_t* a, const uint32_t* b) {
    asm volatile(
        "mma.sync.aligned.m16n8k16.row.col.f32.bf16.bf16.f32 "
        "{%0,%1,%2,%3}, {%4,%5,%6,%7}, {%8,%9}, {%0,%1,%2,%3};"
        : "+f"(c[0]), "+f"(c[1]), "+f"(c[2]), "+f"(c[3])
        : "r"(a[0]), "r"(a[1]), "r"(a[2]), "r"(a[3]), "r"(b[0]), "r"(b[1]));
}
__device__ __forceinline__ void cpasync16(uint32_t saddr, const void* gaddr) {
    asm volatile("cp.async.cg.shared.global [%0], [%1], 16;" :: "r"(saddr), "l"(gaddr));
}
#define CP_COMMIT() asm volatile("cp.async.commit_group;" ::: "memory")
#define CP_WAIT(n)  asm volatile("cp.async.wait_group %0;" :: "n"(n) : "memory")

// ================= split kernels =================
__global__ void __launch_bounds__(256) wsplit_kernel(const float* __restrict__ W, int widx)
{
    const int i = blockIdx.x * 256 + threadIdx.x;          // over Cc*Cc/4
    const float4 v = ((const float4*)W)[i];
    ((uint2*)g_Wh[widx])[i] = make_uint2(f2bf2(v.x, v.y), f2bf2(v.z, v.w));
    ((uint2*)g_Wl[widx])[i] =
        make_uint2(f2bf2(bfres(v.x), bfres(v.y)), f2bf2(bfres(v.z), bfres(v.w)));
}

__global__ void __launch_bounds__(256) asplit_kernel(const float* __restrict__ A)
{
    const int i = blockIdx.x * 256 + threadIdx.x;          // over ROWS*Cc/4
    const float4 v = ((const float4*)A)[i];
    ((uint2*)g_Ah)[i] = make_uint2(f2bf2(v.x, v.y), f2bf2(v.z, v.w));
    ((uint2*)g_Al)[i] =
        make_uint2(f2bf2(bfres(v.x), bfres(v.y)), f2bf2(bfres(v.z), bfres(v.w)));
}

// ================= mma.sync GEMM with cp.async pipeline =================
// C[16384,768] = A*W via 3-term bf16 split: Ah*Wh + Ah*Wl + Al*Wh.
#define KC 32
#define NCHUNK (Cc / KC)           // 24
#define STG 3
#define A_STRIDE 80                // bytes per 32-bf16 row (64B data + 16B pad)
#define B_STRIDE 272               // bytes per 128-bf16 row (256B data + 16B pad)
#define A_TILE (128 * A_STRIDE)    // 10240
#define B_TILE (KC * B_STRIDE)     // 8704
#define STAGEB (2 * A_TILE + 2 * B_TILE)  // 37888
#define GEMM_SMEM (STG * STAGEB)          // 113664

template <int MODE>
__global__ void __launch_bounds__(256) tgemm_kernel(int widx)
{
    extern __shared__ char smem[];
    const uint32_t sb = smem_u32(smem);
    const int tid = threadIdx.x;
    const int lane = tid & 31;
    const int warp = tid >> 5;
    const int wm = warp >> 1;
    const int wn = warp & 1;
    const int blockRow = blockIdx.y * 128;
    const int blockCol = blockIdx.x * 128;

    const __nv_bfloat16* __restrict__ Wh = g_Wh[widx];
    const __nv_bfloat16* __restrict__ Wl = g_Wl[widx];

    float acc[2][8][4];
#pragma unroll
    for (int i = 0; i < 2; i++)
#pragma unroll
        for (int j = 0; j < 8; j++)
#pragma unroll
            for (int t = 0; t < 4; t++) acc[i][j][t] = 0.0f;

    auto load_chunk = [&](int ck, int s) {
        const uint32_t st = sb + s * STAGEB;
        const int k0 = ck * KC;
#pragma unroll
        for (int i = 0; i < 2; i++) {
            const int idx = i * 256 + tid;           // 512 chunks of 16B
            const int row = idx >> 2;                // 0..127
            const int cc = idx & 3;                  // 0..3
            const size_t g = (size_t)(blockRow + row) * Cc + k0 + cc * 8;
            const uint32_t so = row * A_STRIDE + cc * 16;
            cpasync16(st + so, g_Ah + g);
            cpasync16(st + A_TILE + so, g_Al + g);
        }
#pragma unroll
        for (int i = 0; i < 2; i++) {
            const int idx = i * 256 + tid;           // 512 chunks of 16B
            const int kr = idx >> 4;                 // 0..31
            const int nc = idx & 15;                 // 0..15
            const size_t g = (size_t)(k0 + kr) * Cc + blockCol + nc * 8;
            const uint32_t so = kr * B_STRIDE + nc * 16;
            cpasync16(st + 2 * A_TILE + so, Wh + g);
            cpasync16(st + 2 * A_TILE + B_TILE + so, Wl + g);
        }
    };

    // prologue: stages 0..STG-2
#pragma unroll
    for (int s = 0; s < STG - 1; s++) {
        load_chunk(s, s);
        CP_COMMIT();
    }

    for (int it = 0; it < NCHUNK; it++) {
        CP_WAIT(STG - 2);
        __syncthreads();

        const int pre = it + STG - 1;
        if (pre < NCHUNK) load_chunk(pre, pre % STG);
        CP_COMMIT();

        const uint32_t base = sb + (it % STG) * STAGEB;
#pragma unroll
        for (int ks = 0; ks < 2; ks++) {
            uint32_t ah[2][4], al[2][4], bh[4][4], bl[4][4];
#pragma unroll
            for (int mt = 0; mt < 2; mt++) {
                const int row = wm * 32 + mt * 16 + (lane & 15);
                const uint32_t off = row * A_STRIDE + ks * 32 + ((lane >> 4) << 4);
                ldm_x4(ah[mt], base + off);
                ldm_x4(al[mt], base + A_TILE + off);
            }
#pragma unroll
            for (int np = 0; np < 4; np++) {
                const int kr = ks * 16 + (lane & 15);
                const uint32_t off = kr * B_STRIDE + wn * 128 + np * 32 + ((lane >> 4) << 4);
                ldm_x4t(bh[np], base + 2 * A_TILE + off);
                ldm_x4t(bl[np], base + 2 * A_TILE + B_TILE + off);
            }
#pragma unroll
            for (int mt = 0; mt < 2; mt++)
#pragma unroll
                for (int j = 0; j < 8; j++) {
                    const int np = j >> 1;
                    const int hf = (j & 1) << 1;
                    mma16816(acc[mt][j], ah[mt], &bh[np][hf]);
                    mma16816(acc[mt][j], ah[mt], &bl[np][hf]);
                    mma16816(acc[mt][j], al[mt], &bh[np][hf]);
                }
        }
    }

    // epilogue (validated in Round 2)
#pragma unroll
    for (int mt = 0; mt < 2; mt++) {
        const int row0 = blockRow + wm * 32 + mt * 16 + (lane >> 2);
#pragma unroll
        for (int j = 0; j < 8; j++) {
            const int col = blockCol + wn * 64 + j * 8 + ((lane & 3) << 1);
            if (MODE == 0) {
                *(float2*)(g_qp + (size_t)row0 * Cc + col) =
                    make_float2(acc[mt][j][0], acc[mt][j][1]);
                *(float2*)(g_qp + (size_t)(row0 + 8) * Cc + col) =
                    make_float2(acc[mt][j][2], acc[mt][j][3]);
            } else {
#pragma unroll
                for (int e = 0; e < 4; e++) {
                    const int r = row0 + ((e >> 1) << 3);
                    const int cc = col + (e & 1);
                    const int b = r >> 11;
                    const int mm = r & 2047;
                    const int h = cc >> 6;
                    const int dd = cc & 63;
                    const int g = b * Hh + h;
                    const int t = mm * Dd + dd;
                    g_imgT[(size_t)g * IMG_GRP_ELEMS +
                           (size_t)(t & (Mm - 1)) * Dd + (t >> 11)] = acc[mt][j][e];
                }
            }
        }
    }
}

// ---------------- offsets ----------------
__global__ void __launch_bounds__(256) off_kernel(const float* __restrict__ q,
                                                  const float* __restrict__ offW,
                                                  const float* __restrict__ offb)
{
    const int gwarp = (blockIdx.x * blockDim.x + threadIdx.x) >> 5;
    const int lane = threadIdx.x & 31;
    const float* qrow = q + (size_t)gwarp * Cc;
    float a0 = 0.f, a1 = 0.f, a2 = 0.f, a3 = 0.f;
    for (int c = lane; c < Cc; c += 32) {
        const float qv = qrow[c];
        const float* wr = offW + c * (2 * Pp);
        a0 = fmaf(qv, wr[0], a0);
        a1 = fmaf(qv, wr[2], a1);
        a2 = fmaf(qv, wr[4], a2);
        a3 = fmaf(qv, wr[6], a3);
    }
#pragma unroll
    for (int o = 16; o > 0; o >>= 1) {
        a0 += __shfl_xor_sync(0xffffffffu, a0, o);
        a1 += __shfl_xor_sync(0xffffffffu, a1, o);
        a2 += __shfl_xor_sync(0xffffffffu, a2, o);
        a3 += __shfl_xor_sync(0xffffffffu, a3, o);
    }
    if (lane == 0) {
        g_offx[gwarp * 4 + 0] = a0 + offb[0];
        g_offx[gwarp * 4 + 1] = a1 + offb[2];
        g_offx[gwarp * 4 + 2] = a2 + offb[4];
        g_offx[gwarp * 4 + 3] = a3 + offb[6];
    }
}

// ---------------- v column sums: 128 chunks of 16 rows ----------------
__global__ void __launch_bounds__(256) vspart_kernel(const float* __restrict__ v)
{
    const int idx = blockIdx.x * blockDim.x + threadIdx.x;  // Bb*128*192
    const int c4 = idx % (Cc / 4);
    const int chunk = (idx / (Cc / 4)) & 127;
    const int b = idx / ((Cc / 4) * 128);
    const float4* p = (const float4*)(v + ((size_t)b * Mm + (size_t)chunk * 16) * Cc) + c4;
    float4 s = make_float4(0.f, 0.f, 0.f, 0.f);
#pragma unroll
    for (int m = 0; m < 16; m++) {
        float4 t = p[(size_t)m * (Cc / 4)];
        s.x += t.x; s.y += t.y; s.z += t.z; s.w += t.w;
    }
    ((float4*)g_vspart)[idx] = s;
}

__global__ void __launch_bounds__(256) vsred_kernel()
{
    const int idx = blockIdx.x * blockDim.x + threadIdx.x;  // Bb*Cc
    const int c = idx % Cc;
    const int b = idx / Cc;
    float s = 0.f;
#pragma unroll 8
    for (int ch = 0; ch < 128; ch++) s += g_vspart[((size_t)b * 128 + ch) * Cc + c];
    g_vs[idx] = s;
}

// ---------------- pv ----------------
__global__ void __launch_bounds__(256) pv_kernel(const float* __restrict__ vW,
                                                 const float* __restrict__ projW)
{
    __shared__ float vs_s[Cc];
    __shared__ float vsum_s[Cc];
    const int b = blockIdx.x;
    for (int i = threadIdx.x; i < Cc; i += 256) vs_s[i] = g_vs[b * Cc + i];
    __syncthreads();
    for (int o = threadIdx.x; o < Cc; o += 256) {
        float s = 0.f;
        for (int c = 0; c < Cc; c++) s = fmaf(vs_s[c], vW[(size_t)c * Cc + o], s);
        vsum_s[o] = s;
    }
    __syncthreads();
    for (int o = threadIdx.x; o < Hh * Cc; o += 256) {
        const int h = o / Cc;
        const int c = o % Cc;
        float s = 0.f;
#pragma unroll
        for (int d = 0; d < Dd; d++)
            s = fmaf(vsum_s[h * Dd + d], projW[(size_t)(h * Dd + d) * Cc + c], s);
        g_pv[(size_t)b * Hh * Cc + o] = s;
    }
}

// ---------------- sampling + dot ----------------
__global__ void __launch_bounds__(256) sample_kernel()
{
    const int gwarp = (blockIdx.x * blockDim.x + threadIdx.x) >> 5;
    const int lane = threadIdx.x & 31;
    const int g = gwarp >> 11;
    const int n2 = gwarp & 2047;
    const int b = g / Hh;
    const int h = g % Hh;
    const int nq = (h * Nn + n2) / Hh;

    const float* imgg = g_imgT + (size_t)g * IMG_GRP_ELEMS;
    float accx = 0.f, accy = 0.f;
#pragma unroll
    for (int p = 0; p < Pp; p++) {
        const float offx = g_offx[((size_t)b * Nn + nq) * Pp + p];
        const float gx = offx / 2047.0f * 2.0f - 1.0f;
        const float x = (gx + 1.0f) * 0.5f * 2047.0f;
        const float x0f = floorf(x);
        const float w = x - x0f;
        const int x0 = (int)x0f;
        const int x1 = x0 + 1;
        const float w0 = (x0 >= 0 && x0 < Mm) ? (1.0f - w) : 0.0f;
        const float w1 = (x1 >= 0 && x1 < Mm) ? w : 0.0f;
        const int x0c = min(max(x0, 0), Mm - 1);
        const int x1c = min(max(x1, 0), Mm - 1);
        const float2 v0 = *(const float2*)(imgg + (size_t)x0c * Dd + 2 * lane);
        const float2 v1 = *(const float2*)(imgg + (size_t)x1c * Dd + 2 * lane);
        accx += w0 * v0.x + w1 * v1.x;
        accy += w0 * v0.y + w1 * v1.y;
    }
    const float2 qv =
        *(const float2*)(g_qp + ((size_t)b * Nn + n2) * Cc + h * Dd + 2 * lane);
    float partial = accx * qv.x + accy * qv.y;
#pragma unroll
    for (int o = 16; o > 0; o >>= 1) partial += __shfl_xor_sync(0xffffffffu, partial, o);
    if (lane == 0) g_logits[gwarp] = partial * (0.125f * 0.25f);
}

// ---------------- softmax ----------------
__global__ void __launch_bounds__(256) softmax_kernel()
{
    __shared__ float red[256];
    const int row = blockIdx.x;
    float* ptr = g_logits + (size_t)row * Nn;
    const int tid = threadIdx.x;
    float vals[8];
    float m = -1e30f;
#pragma unroll
    for (int i = 0; i < 8; i++) {
        vals[i] = ptr[tid + i * 256];
        m = fmaxf(m, vals[i]);
    }
    red[tid] = m;
    __syncthreads();
    for (int s = 128; s > 0; s >>= 1) {
        if (tid < s) red[tid] = fmaxf(red[tid], red[tid + s]);
        __syncthreads();
    }
    m = red[0];
    __syncthreads();
    float sum = 0.f;
#pragma unroll
    for (int i = 0; i < 8; i++) {
        vals[i] = expf(vals[i] - m);
        sum += vals[i];
    }
    red[tid] = sum;
    __syncthreads();
    for (int s = 128; s > 0; s >>= 1) {
        if (tid < s) red[tid] += red[tid + s];
        __syncthreads();
    }
    const float inv = 1.0f / red[0];
#pragma unroll
    for (int i = 0; i < 8; i++) ptr[tid + i * 256] = vals[i] * inv;
}

// ---------------- output ----------------
#define OUT_ROWS 32
__global__ void __launch_bounds__(256) out_kernel(const float* __restrict__ projb,
                                                  float* __restrict__ out)
{
    __shared__ float pv_s[Hh * Cc];
    __shared__ float a_s[Hh];
    const int b = blockIdx.y;
    const int n0 = blockIdx.x * OUT_ROWS;
    const int tid = threadIdx.x;
    for (int i = tid; i < Hh * Cc; i += 256) pv_s[i] = g_pv[(size_t)b * Hh * Cc + i];
    __syncthreads();
    for (int n = n0; n < n0 + OUT_ROWS; n++) {
        __syncthreads();
        if (tid < Hh) a_s[tid] = g_logits[((size_t)b * Hh + tid) * Nn + n];
        __syncthreads();
        for (int c = tid; c < Cc; c += 256) {
            float s = projb[c];
#pragma unroll
            for (int h = 0; h < Hh; h++) s = fmaf(a_s[h], pv_s[h * Cc + c], s);
            out[((size_t)b * Nn + n) * Cc + c] = s;
        }
    }
}

// ---------------- launch ----------------
extern "C" void kernel_launch(void* const* d_in, const int* in_sizes, int n_in,
                              void* d_out, int out_size)
{
    (void)in_sizes; (void)n_in; (void)out_size;
    const float* q     = (const float*)d_in[0];
    const float* k     = (const float*)d_in[1];
    const float* v     = (const float*)d_in[2];
    const float* qW    = (const float*)d_in[3];
    const float* kW    = (const float*)d_in[4];
    const float* vW    = (const float*)d_in[5];
    const float* offW  = (const float*)d_in[6];
    const float* offb  = (const float*)d_in[7];
    const float* projW = (const float*)d_in[8];
    const float* projb = (const float*)d_in[9];
    float* out = (float*)d_out;

    cudaFuncSetAttribute(tgemm_kernel<0>, cudaFuncAttributeMaxDynamicSharedMemorySize,
                         GEMM_SMEM);
    cudaFuncSetAttribute(tgemm_kernel<1>, cudaFuncAttributeMaxDynamicSharedMemorySize,
                         GEMM_SMEM);

    dim3 ggrid(Cc / 128, ROWS / 128);                       // (6, 128)
    wsplit_kernel<<<Cc * Cc / 4 / 256, 256>>>(qW, 0);       // 1
    wsplit_kernel<<<Cc * Cc / 4 / 256, 256>>>(kW, 1);       // 2
    asplit_kernel<<<ROWS * Cc / 4 / 256, 256>>>(k);         // 3
    tgemm_kernel<1><<<ggrid, 256, GEMM_SMEM>>>(1);          // 4: kp -> imgT (profiled)
    asplit_kernel<<<ROWS * Cc / 4 / 256, 256>>>(q);         // 5
    tgemm_kernel<0><<<ggrid, 256, GEMM_SMEM>>>(0);          // 6: qp
    off_kernel<<<ROWS / 8, 256>>>(q, offW, offb);
    vspart_kernel<<<(Bb * 128 * (Cc / 4)) / 256, 256>>>(v);
    vsred_kernel<<<(Bb * Cc) / 256, 256>>>();
    sample_kernel<<<(GRP * Nn) / 8, 256>>>();
    softmax_kernel<<<GRP, 256>>>();
    pv_kernel<<<Bb, 256>>>(vW, projW);
    out_kernel<<<dim3(Nn / OUT_ROWS, Bb), 256>>>(projb, out);
}

// round 5
// speedup vs baseline: 2.7820x; 1.3364x over previous
#include <cuda_runtime.h>
#include <cuda_fp16.h>
#include <cstdint>

// Problem constants
#define Bb 8
#define Nn 2048
#define Mm 2048
#define Cc 768
#define Hh 12
#define Pp 4
#define Dd 64
#define ROWS (Bb * Nn)
#define GRP  (Bb * Hh)
#define IMG_GRP_ELEMS (Mm * Dd)

// ---------------- device scratch ----------------
__device__ float g_qp[ROWS * Cc];
__device__ float g_imgT[GRP * IMG_GRP_ELEMS];
__device__ float g_offx[ROWS * Pp];
__device__ float g_logits[GRP * Nn];
__device__ float g_vspart[Bb * 128 * Cc];
__device__ float g_vs[Bb * Cc];
__device__ float g_pv[Bb * Hh * Cc];
__device__ __half g_Ah[2][ROWS * Cc];      // [0]=q, [1]=k  (fp16 activations)
__device__ __half g_Wh[2][Cc * Cc];        // [0]=qW, [1]=kW (fp16 weights, [k][n])

// ================= helpers =================
__device__ __forceinline__ uint32_t smem_u32(const void* p) {
    uint32_t a;
    asm("{ .reg .u64 t; cvta.to.shared.u64 t, %1; cvt.u32.u64 %0, t; }"
        : "=r"(a) : "l"(p));
    return a;
}
__device__ __forceinline__ uint32_t f2h2(float x, float y) {
    __half2 t = __floats2half2_rn(x, y);
    return *reinterpret_cast<uint32_t*>(&t);
}
__device__ __forceinline__ void ldm_x4(uint32_t* r, uint32_t addr) {
    asm volatile("ldmatrix.sync.aligned.m8n8.x4.shared.b16 {%0,%1,%2,%3}, [%4];"
                 : "=r"(r[0]), "=r"(r[1]), "=r"(r[2]), "=r"(r[3]) : "r"(addr));
}
__device__ __forceinline__ void ldm_x4t(uint32_t* r, uint32_t addr) {
    asm volatile("ldmatrix.sync.aligned.m8n8.x4.trans.shared.b16 {%0,%1,%2,%3}, [%4];"
                 : "=r"(r[0]), "=r"(r[1]), "=r"(r[2]), "=r"(r[3]) : "r"(addr));
}
__device__ __forceinline__ void mma16816(float* c, const uint32_t* a, const uint32_t* b) {
    asm volatile(
        "mma.sync.aligned.m16n8k16.row.col.f32.f16.f16.f32 "
        "{%0,%1,%2,%3}, {%4,%5,%6,%7}, {%8,%9}, {%0,%1,%2,%3};"
        : "+f"(c[0]), "+f"(c[1]), "+f"(c[2]), "+f"(c[3])
        : "r"(a[0]), "r"(a[1]), "r"(a[2]), "r"(a[3]), "r"(b[0]), "r"(b[1]));
}
__device__ __forceinline__ void cpasync16(uint32_t saddr, const void* gaddr) {
    asm volatile("cp.async.cg.shared.global [%0], [%1], 16;" :: "r"(saddr), "l"(gaddr));
}
#define CP_COMMIT() asm volatile("cp.async.commit_group;" ::: "memory")
#define CP_WAIT(n)  asm volatile("cp.async.wait_group %0;" :: "n"(n) : "memory")

// ================= fp32 -> fp16 conversion kernels =================
__global__ void __launch_bounds__(256) wconv_kernel(const float* __restrict__ W, int widx)
{
    const int i = blockIdx.x * 256 + threadIdx.x;          // over Cc*Cc/4
    const float4 v = ((const float4*)W)[i];
    ((uint2*)g_Wh[widx])[i] = make_uint2(f2h2(v.x, v.y), f2h2(v.z, v.w));
}
__global__ void __launch_bounds__(256) aconv_kernel(const float* __restrict__ A, int aidx)
{
    const int i = blockIdx.x * 256 + threadIdx.x;          // over ROWS*Cc/4
    const float4 v = ((const float4*)A)[i];
    ((uint2*)g_Ah[aidx])[i] = make_uint2(f2h2(v.x, v.y), f2h2(v.z, v.w));
}

// ================= fp16 mma.sync GEMM with cp.async pipeline =================
#define KC 32
#define NCHUNK (Cc / KC)           // 24
#define STG 4
#define A_STRIDE 80                // bytes per 32-half row (64B data + 16B pad)
#define B_STRIDE 272               // bytes per 128-half row (256B data + 16B pad)
#define A_TILE (128 * A_STRIDE)    // 10240
#define B_TILE (KC * B_STRIDE)     // 8704
#define STAGEB (A_TILE + B_TILE)   // 18944
#define GEMM_SMEM (STG * STAGEB)   // 75776

template <int MODE>
__global__ void __launch_bounds__(256) tgemm_kernel(int idx)
{
    extern __shared__ char smem[];
    const uint32_t sb = smem_u32(smem);
    const int tid = threadIdx.x;
    const int lane = tid & 31;
    const int warp = tid >> 5;
    const int wm = warp >> 1;
    const int wn = warp & 1;
    const int blockRow = blockIdx.y * 128;
    const int blockCol = blockIdx.x * 128;

    const __half* __restrict__ Ah = g_Ah[idx];
    const __half* __restrict__ Wh = g_Wh[idx];

    float acc[2][8][4];
#pragma unroll
    for (int i = 0; i < 2; i++)
#pragma unroll
        for (int j = 0; j < 8; j++)
#pragma unroll
            for (int t = 0; t < 4; t++) acc[i][j][t] = 0.0f;

    auto load_chunk = [&](int ck, int s) {
        const uint32_t st = sb + s * STAGEB;
        const int k0 = ck * KC;
        // A tile: 128 rows x 32 half (64B/row) = 512 x 16B -> 2 per thread
#pragma unroll
        for (int i = 0; i < 2; i++) {
            const int idx2 = i * 256 + tid;
            const int row = idx2 >> 2;               // 0..127
            const int cc = idx2 & 3;                 // 0..3
            cpasync16(st + row * A_STRIDE + cc * 16,
                      Ah + (size_t)(blockRow + row) * Cc + k0 + cc * 8);
        }
        // B tile: 32 rows x 128 half (256B/row) = 512 x 16B -> 2 per thread
#pragma unroll
        for (int i = 0; i < 2; i++) {
            const int idx2 = i * 256 + tid;
            const int kr = idx2 >> 4;                // 0..31
            const int nc = idx2 & 15;                // 0..15
            cpasync16(st + A_TILE + kr * B_STRIDE + nc * 16,
                      Wh + (size_t)(k0 + kr) * Cc + blockCol + nc * 8);
        }
    };

    // prologue
#pragma unroll
    for (int s = 0; s < STG - 1; s++) {
        load_chunk(s, s);
        CP_COMMIT();
    }

    for (int it = 0; it < NCHUNK; it++) {
        CP_WAIT(STG - 2);
        __syncthreads();

        const int pre = it + STG - 1;
        if (pre < NCHUNK) load_chunk(pre, pre % STG);
        CP_COMMIT();

        const uint32_t base = sb + (it % STG) * STAGEB;
#pragma unroll
        for (int ks = 0; ks < 2; ks++) {
            uint32_t ah[2][4], bh[4][4];
#pragma unroll
            for (int mt = 0; mt < 2; mt++) {
                const int row = wm * 32 + mt * 16 + (lane & 15);
                ldm_x4(ah[mt], base + row * A_STRIDE + ks * 32 + ((lane >> 4) << 4));
            }
#pragma unroll
            for (int np = 0; np < 4; np++) {
                const int kr = ks * 16 + (lane & 15);
                ldm_x4t(bh[np], base + A_TILE + kr * B_STRIDE + wn * 128 + np * 32 +
                                ((lane >> 4) << 4));
            }
#pragma unroll
            for (int mt = 0; mt < 2; mt++)
#pragma unroll
                for (int j = 0; j < 8; j++)
                    mma16816(acc[mt][j], ah[mt], &bh[j >> 1][(j & 1) << 1]);
        }
    }

    // epilogue (layout identical to validated R2/R4)
#pragma unroll
    for (int mt = 0; mt < 2; mt++) {
        const int row0 = blockRow + wm * 32 + mt * 16 + (lane >> 2);
#pragma unroll
        for (int j = 0; j < 8; j++) {
            const int col = blockCol + wn * 64 + j * 8 + ((lane & 3) << 1);
            if (MODE == 0) {
                *(float2*)(g_qp + (size_t)row0 * Cc + col) =
                    make_float2(acc[mt][j][0], acc[mt][j][1]);
                *(float2*)(g_qp + (size_t)(row0 + 8) * Cc + col) =
                    make_float2(acc[mt][j][2], acc[mt][j][3]);
            } else {
#pragma unroll
                for (int e = 0; e < 4; e++) {
                    const int r = row0 + ((e >> 1) << 3);
                    const int cc = col + (e & 1);
                    const int b = r >> 11;
                    const int mm = r & 2047;
                    const int h = cc >> 6;
                    const int dd = cc & 63;
                    const int g = b * Hh + h;
                    const int t = mm * Dd + dd;
                    g_imgT[(size_t)g * IMG_GRP_ELEMS +
                           (size_t)(t & (Mm - 1)) * Dd + (t >> 11)] = acc[mt][j][e];
                }
            }
        }
    }
}

// ---------------- offsets ----------------
__global__ void __launch_bounds__(256) off_kernel(const float* __restrict__ q,
                                                  const float* __restrict__ offW,
                                                  const float* __restrict__ offb)
{
    const int gwarp = (blockIdx.x * blockDim.x + threadIdx.x) >> 5;
    const int lane = threadIdx.x & 31;
    const float* qrow = q + (size_t)gwarp * Cc;
    float a0 = 0.f, a1 = 0.f, a2 = 0.f, a3 = 0.f;
    for (int c = lane; c < Cc; c += 32) {
        const float qv = qrow[c];
        const float* wr = offW + c * (2 * Pp);
        a0 = fmaf(qv, wr[0], a0);
        a1 = fmaf(qv, wr[2], a1);
        a2 = fmaf(qv, wr[4], a2);
        a3 = fmaf(qv, wr[6], a3);
    }
#pragma unroll
    for (int o = 16; o > 0; o >>= 1) {
        a0 += __shfl_xor_sync(0xffffffffu, a0, o);
        a1 += __shfl_xor_sync(0xffffffffu, a1, o);
        a2 += __shfl_xor_sync(0xffffffffu, a2, o);
        a3 += __shfl_xor_sync(0xffffffffu, a3, o);
    }
    if (lane == 0) {
        g_offx[gwarp * 4 + 0] = a0 + offb[0];
        g_offx[gwarp * 4 + 1] = a1 + offb[2];
        g_offx[gwarp * 4 + 2] = a2 + offb[4];
        g_offx[gwarp * 4 + 3] = a3 + offb[6];
    }
}

// ---------------- v column sums ----------------
__global__ void __launch_bounds__(256) vspart_kernel(const float* __restrict__ v)
{
    const int idx = blockIdx.x * blockDim.x + threadIdx.x;
    const int c4 = idx % (Cc / 4);
    const int chunk = (idx / (Cc / 4)) & 127;
    const int b = idx / ((Cc / 4) * 128);
    const float4* p = (const float4*)(v + ((size_t)b * Mm + (size_t)chunk * 16) * Cc) + c4;
    float4 s = make_float4(0.f, 0.f, 0.f, 0.f);
#pragma unroll
    for (int m = 0; m < 16; m++) {
        float4 t = p[(size_t)m * (Cc / 4)];
        s.x += t.x; s.y += t.y; s.z += t.z; s.w += t.w;
    }
    ((float4*)g_vspart)[idx] = s;
}

__global__ void __launch_bounds__(256) vsred_kernel()
{
    const int idx = blockIdx.x * blockDim.x + threadIdx.x;
    const int c = idx % Cc;
    const int b = idx / Cc;
    float s = 0.f;
#pragma unroll 8
    for (int ch = 0; ch < 128; ch++) s += g_vspart[((size_t)b * 128 + ch) * Cc + c];
    g_vs[idx] = s;
}

// ---------------- pv ----------------
__global__ void __launch_bounds__(256) pv_kernel(const float* __restrict__ vW,
                                                 const float* __restrict__ projW)
{
    __shared__ float vs_s[Cc];
    __shared__ float vsum_s[Cc];
    const int b = blockIdx.x;
    for (int i = threadIdx.x; i < Cc; i += 256) vs_s[i] = g_vs[b * Cc + i];
    __syncthreads();
    for (int o = threadIdx.x; o < Cc; o += 256) {
        float s = 0.f;
        for (int c = 0; c < Cc; c++) s = fmaf(vs_s[c], vW[(size_t)c * Cc + o], s);
        vsum_s[o] = s;
    }
    __syncthreads();
    for (int o = threadIdx.x; o < Hh * Cc; o += 256) {
        const int h = o / Cc;
        const int c = o % Cc;
        float s = 0.f;
#pragma unroll
        for (int d = 0; d < Dd; d++)
            s = fmaf(vsum_s[h * Dd + d], projW[(size_t)(h * Dd + d) * Cc + c], s);
        g_pv[(size_t)b * Hh * Cc + o] = s;
    }
}

// ---------------- sampling + dot ----------------
__global__ void __launch_bounds__(256) sample_kernel()
{
    const int gwarp = (blockIdx.x * blockDim.x + threadIdx.x) >> 5;
    const int lane = threadIdx.x & 31;
    const int g = gwarp >> 11;
    const int n2 = gwarp & 2047;
    const int b = g / Hh;
    const int h = g % Hh;
    const int nq = (h * Nn + n2) / Hh;

    const float* imgg = g_imgT + (size_t)g * IMG_GRP_ELEMS;
    float accx = 0.f, accy = 0.f;
#pragma unroll
    for (int p = 0; p < Pp; p++) {
        const float offx = g_offx[((size_t)b * Nn + nq) * Pp + p];
        const float gx = offx / 2047.0f * 2.0f - 1.0f;
        const float x = (gx + 1.0f) * 0.5f * 2047.0f;
        const float x0f = floorf(x);
        const float w = x - x0f;
        const int x0 = (int)x0f;
        const int x1 = x0 + 1;
        const float w0 = (x0 >= 0 && x0 < Mm) ? (1.0f - w) : 0.0f;
        const float w1 = (x1 >= 0 && x1 < Mm) ? w : 0.0f;
        const int x0c = min(max(x0, 0), Mm - 1);
        const int x1c = min(max(x1, 0), Mm - 1);
        const float2 v0 = *(const float2*)(imgg + (size_t)x0c * Dd + 2 * lane);
        const float2 v1 = *(const float2*)(imgg + (size_t)x1c * Dd + 2 * lane);
        accx += w0 * v0.x + w1 * v1.x;
        accy += w0 * v0.y + w1 * v1.y;
    }
    const float2 qv =
        *(const float2*)(g_qp + ((size_t)b * Nn + n2) * Cc + h * Dd + 2 * lane);
    float partial = accx * qv.x + accy * qv.y;
#pragma unroll
    for (int o = 16; o > 0; o >>= 1) partial += __shfl_xor_sync(0xffffffffu, partial, o);
    if (lane == 0) g_logits[gwarp] = partial * (0.125f * 0.25f);
}

// ---------------- softmax ----------------
__global__ void __launch_bounds__(256) softmax_kernel()
{
    __shared__ float red[256];
    const int row = blockIdx.x;
    float* ptr = g_logits + (size_t)row * Nn;
    const int tid = threadIdx.x;
    float vals[8];
    float m = -1e30f;
#pragma unroll
    for (int i = 0; i < 8; i++) {
        vals[i] = ptr[tid + i * 256];
        m = fmaxf(m, vals[i]);
    }
    red[tid] = m;
    __syncthreads();
    for (int s = 128; s > 0; s >>= 1) {
        if (tid < s) red[tid] = fmaxf(red[tid], red[tid + s]);
        __syncthreads();
    }
    m = red[0];
    __syncthreads();
    float sum = 0.f;
#pragma unroll
    for (int i = 0; i < 8; i++) {
        vals[i] = expf(vals[i] - m);
        sum += vals[i];
    }
    red[tid] = sum;
    __syncthreads();
    for (int s = 128; s > 0; s >>= 1) {
        if (tid < s) red[tid] += red[tid + s];
        __syncthreads();
    }
    const float inv = 1.0f / red[0];
#pragma unroll
    for (int i = 0; i < 8; i++) ptr[tid + i * 256] = vals[i] * inv;
}

// ---------------- output ----------------
#define OUT_ROWS 32
__global__ void __launch_bounds__(256) out_kernel(const float* __restrict__ projb,
                                                  float* __restrict__ out)
{
    __shared__ float pv_s[Hh * Cc];
    __shared__ float a_s[Hh];
    const int b = blockIdx.y;
    const int n0 = blockIdx.x * OUT_ROWS;
    const int tid = threadIdx.x;
    for (int i = tid; i < Hh * Cc; i += 256) pv_s[i] = g_pv[(size_t)b * Hh * Cc + i];
    __syncthreads();
    for (int n = n0; n < n0 + OUT_ROWS; n++) {
        __syncthreads();
        if (tid < Hh) a_s[tid] = g_logits[((size_t)b * Hh + tid) * Nn + n];
        __syncthreads();
        for (int c = tid; c < Cc; c += 256) {
            float s = projb[c];
#pragma unroll
            for (int h = 0; h < Hh; h++) s = fmaf(a_s[h], pv_s[h * Cc + c], s);
            out[((size_t)b * Nn + n) * Cc + c] = s;
        }
    }
}

// ---------------- launch ----------------
extern "C" void kernel_launch(void* const* d_in, const int* in_sizes, int n_in,
                              void* d_out, int out_size)
{
    (void)in_sizes; (void)n_in; (void)out_size;
    const float* q     = (const float*)d_in[0];
    const float* k     = (const float*)d_in[1];
    const float* v     = (const float*)d_in[2];
    const float* qW    = (const float*)d_in[3];
    const float* kW    = (const float*)d_in[4];
    const float* vW    = (const float*)d_in[5];
    const float* offW  = (const float*)d_in[6];
    const float* offb  = (const float*)d_in[7];
    const float* projW = (const float*)d_in[8];
    const float* projb = (const float*)d_in[9];
    float* out = (float*)d_out;

    cudaFuncSetAttribute(tgemm_kernel<0>, cudaFuncAttributeMaxDynamicSharedMemorySize,
                         GEMM_SMEM);
    cudaFuncSetAttribute(tgemm_kernel<1>, cudaFuncAttributeMaxDynamicSharedMemorySize,
                         GEMM_SMEM);

    dim3 ggrid(Cc / 128, ROWS / 128);                       // (6, 128)
    wconv_kernel<<<Cc * Cc / 4 / 256, 256>>>(qW, 0);        // 1
    wconv_kernel<<<Cc * Cc / 4 / 256, 256>>>(kW, 1);        // 2
    aconv_kernel<<<ROWS * Cc / 4 / 256, 256>>>(k, 1);       // 3
    tgemm_kernel<1><<<ggrid, 256, GEMM_SMEM>>>(1);          // 4: kp -> imgT (profiled)
    aconv_kernel<<<ROWS * Cc / 4 / 256, 256>>>(q, 0);       // 5
    tgemm_kernel<0><<<ggrid, 256, GEMM_SMEM>>>(0);          // 6: qp
    off_kernel<<<ROWS / 8, 256>>>(q, offW, offb);
    vspart_kernel<<<(Bb * 128 * (Cc / 4)) / 256, 256>>>(v);
    vsred_kernel<<<(Bb * Cc) / 256, 256>>>();
    sample_kernel<<<(GRP * Nn) / 8, 256>>>();
    softmax_kernel<<<GRP, 256>>>();
    pv_kernel<<<Bb, 256>>>(vW, projW);
    out_kernel<<<dim3(Nn / OUT_ROWS, Bb), 256>>>(projb, out);
}

// round 6
// speedup vs baseline: 2.7947x; 1.0046x over previous
#include <cuda_runtime.h>
#include <cuda_fp16.h>
#include <cstdint>

// Problem constants
#define Bb 8
#define Nn 2048
#define Mm 2048
#define Cc 768
#define Hh 12
#define Pp 4
#define Dd 64
#define ROWS (Bb * Nn)
#define GRP  (Bb * Hh)
#define IMG_GRP_ELEMS (Mm * Dd)

// ---------------- device scratch ----------------
__device__ float g_qp[ROWS * Cc];
__device__ float g_imgT[GRP * IMG_GRP_ELEMS];
__device__ float g_offx[ROWS * Pp];
__device__ float g_logits[GRP * Nn];
__device__ float g_vspart[Bb * 128 * Cc];
__device__ float g_vs[Bb * Cc];
__device__ float g_pv[Bb * Hh * Cc];
__device__ __half g_Ah[2][ROWS * Cc];      // [0]=q, [1]=k  (fp16 activations)
__device__ __half g_Wh[2][Cc * Cc];        // [0]=qW, [1]=kW (fp16 weights, [k][n])

// ================= helpers =================
__device__ __forceinline__ uint32_t smem_u32(const void* p) {
    uint32_t a;
    asm("{ .reg .u64 t; cvta.to.shared.u64 t, %1; cvt.u32.u64 %0, t; }"
        : "=r"(a) : "l"(p));
    return a;
}
__device__ __forceinline__ uint32_t f2h2(float x, float y) {
    __half2 t = __floats2half2_rn(x, y);
    return *reinterpret_cast<uint32_t*>(&t);
}
__device__ __forceinline__ void ldm_x4(uint32_t* r, uint32_t addr) {
    asm volatile("ldmatrix.sync.aligned.m8n8.x4.shared.b16 {%0,%1,%2,%3}, [%4];"
                 : "=r"(r[0]), "=r"(r[1]), "=r"(r[2]), "=r"(r[3]) : "r"(addr));
}
__device__ __forceinline__ void ldm_x4t(uint32_t* r, uint32_t addr) {
    asm volatile("ldmatrix.sync.aligned.m8n8.x4.trans.shared.b16 {%0,%1,%2,%3}, [%4];"
                 : "=r"(r[0]), "=r"(r[1]), "=r"(r[2]), "=r"(r[3]) : "r"(addr));
}
__device__ __forceinline__ void mma16816(float* c, const uint32_t* a, const uint32_t* b) {
    asm volatile(
        "mma.sync.aligned.m16n8k16.row.col.f32.f16.f16.f32 "
        "{%0,%1,%2,%3}, {%4,%5,%6,%7}, {%8,%9}, {%0,%1,%2,%3};"
        : "+f"(c[0]), "+f"(c[1]), "+f"(c[2]), "+f"(c[3])
        : "r"(a[0]), "r"(a[1]), "r"(a[2]), "r"(a[3]), "r"(b[0]), "r"(b[1]));
}
__device__ __forceinline__ void cpasync16(uint32_t saddr, const void* gaddr) {
    asm volatile("cp.async.cg.shared.global [%0], [%1], 16;" :: "r"(saddr), "l"(gaddr));
}
#define CP_COMMIT() asm volatile("cp.async.commit_group;" ::: "memory")
#define CP_WAIT(n)  asm volatile("cp.async.wait_group %0;" :: "n"(n) : "memory")

// ================= fp32 -> fp16 conversion kernels =================
__global__ void __launch_bounds__(256) wconv_kernel(const float* __restrict__ W, int widx)
{
    const int i = blockIdx.x * 256 + threadIdx.x;
    const float4 v = ((const float4*)W)[i];
    ((uint2*)g_Wh[widx])[i] = make_uint2(f2h2(v.x, v.y), f2h2(v.z, v.w));
}
__global__ void __launch_bounds__(256) aconv_kernel(const float* __restrict__ A, int aidx)
{
    const int i = blockIdx.x * 256 + threadIdx.x;
    const float4 v = ((const float4*)A)[i];
    ((uint2*)g_Ah[aidx])[i] = make_uint2(f2h2(v.x, v.y), f2h2(v.z, v.w));
}

// ================= fp16 mma.sync GEMM, 256x128 tile =================
#define KC 64
#define NCHUNK (Cc / KC)           // 12
#define STG 3
#define A_STRIDE 144               // bytes per 64-half row (128B data + 16B pad)
#define B_STRIDE 272               // bytes per 128-half row (256B data + 16B pad)
#define A_TILE (256 * A_STRIDE)    // 36864
#define B_TILE (KC * B_STRIDE)     // 17408
#define STAGEB (A_TILE + B_TILE)   // 54272
#define GEMM_SMEM (STG * STAGEB)   // 162816

template <int MODE>
__global__ void __launch_bounds__(256) tgemm_kernel(int idx)
{
    extern __shared__ char smem[];
    const uint32_t sb = smem_u32(smem);
    const int tid = threadIdx.x;
    const int lane = tid & 31;
    const int warp = tid >> 5;
    const int wm = warp >> 1;          // 0..3, 64 rows each
    const int wn = warp & 1;           // 0..1, 64 cols each
    const int blockRow = blockIdx.y * 256;
    const int blockCol = blockIdx.x * 128;

    const __half* __restrict__ Ah = g_Ah[idx];
    const __half* __restrict__ Wh = g_Wh[idx];

    float acc[4][8][4];
#pragma unroll
    for (int i = 0; i < 4; i++)
#pragma unroll
        for (int j = 0; j < 8; j++)
#pragma unroll
            for (int t = 0; t < 4; t++) acc[i][j][t] = 0.0f;

    auto load_chunk = [&](int ck, int s) {
        const uint32_t st = sb + s * STAGEB;
        const int k0 = ck * KC;
        // A tile: 256 rows x 64 half (128B/row) = 2048 x 16B -> 8 per thread
#pragma unroll
        for (int i = 0; i < 8; i++) {
            const int idx2 = i * 256 + tid;
            const int row = idx2 >> 3;               // 0..255
            const int cc = idx2 & 7;                 // 0..7
            cpasync16(st + row * A_STRIDE + cc * 16,
                      Ah + (size_t)(blockRow + row) * Cc + k0 + cc * 8);
        }
        // B tile: 64 rows x 128 half (256B/row) = 1024 x 16B -> 4 per thread
#pragma unroll
        for (int i = 0; i < 4; i++) {
            const int idx2 = i * 256 + tid;
            const int kr = idx2 >> 4;                // 0..63
            const int nc = idx2 & 15;                // 0..15
            cpasync16(st + A_TILE + kr * B_STRIDE + nc * 16,
                      Wh + (size_t)(k0 + kr) * Cc + blockCol + nc * 8);
        }
    };

    // prologue
#pragma unroll
    for (int s = 0; s < STG - 1; s++) {
        load_chunk(s, s);
        CP_COMMIT();
    }

    for (int it = 0; it < NCHUNK; it++) {
        CP_WAIT(STG - 2);
        __syncthreads();

        const int pre = it + STG - 1;
        if (pre < NCHUNK) load_chunk(pre, pre % STG);
        CP_COMMIT();

        const uint32_t base = sb + (it % STG) * STAGEB;
#pragma unroll
        for (int ks = 0; ks < 4; ks++) {
            uint32_t ah[4][4], bh[4][4];
#pragma unroll
            for (int mt = 0; mt < 4; mt++) {
                const int row = wm * 64 + mt * 16 + (lane & 15);
                ldm_x4(ah[mt], base + row * A_STRIDE + ks * 32 + ((lane >> 4) << 4));
            }
#pragma unroll
            for (int np = 0; np < 4; np++) {
                const int kr = ks * 16 + (lane & 15);
                ldm_x4t(bh[np], base + A_TILE + kr * B_STRIDE + wn * 128 + np * 32 +
                                ((lane >> 4) << 4));
            }
#pragma unroll
            for (int mt = 0; mt < 4; mt++)
#pragma unroll
                for (int j = 0; j < 8; j++)
                    mma16816(acc[mt][j], ah[mt], &bh[j >> 1][(j & 1) << 1]);
        }
    }

    // epilogue
#pragma unroll
    for (int mt = 0; mt < 4; mt++) {
        const int row0 = blockRow + wm * 64 + mt * 16 + (lane >> 2);
#pragma unroll
        for (int j = 0; j < 8; j++) {
            const int col = blockCol + wn * 64 + j * 8 + ((lane & 3) << 1);
            if (MODE == 0) {
                *(float2*)(g_qp + (size_t)row0 * Cc + col) =
                    make_float2(acc[mt][j][0], acc[mt][j][1]);
                *(float2*)(g_qp + (size_t)(row0 + 8) * Cc + col) =
                    make_float2(acc[mt][j][2], acc[mt][j][3]);
            } else {
#pragma unroll
                for (int e = 0; e < 4; e++) {
                    const int r = row0 + ((e >> 1) << 3);
                    const int cc = col + (e & 1);
                    const int b = r >> 11;
                    const int mm = r & 2047;
                    const int h = cc >> 6;
                    const int dd = cc & 63;
                    const int g = b * Hh + h;
                    const int t = mm * Dd + dd;
                    g_imgT[(size_t)g * IMG_GRP_ELEMS +
                           (size_t)(t & (Mm - 1)) * Dd + (t >> 11)] = acc[mt][j][e];
                }
            }
        }
    }
}

// ---------------- offsets ----------------
__global__ void __launch_bounds__(256) off_kernel(const float* __restrict__ q,
                                                  const float* __restrict__ offW,
                                                  const float* __restrict__ offb)
{
    const int gwarp = (blockIdx.x * blockDim.x + threadIdx.x) >> 5;
    const int lane = threadIdx.x & 31;
    const float* qrow = q + (size_t)gwarp * Cc;
    float a0 = 0.f, a1 = 0.f, a2 = 0.f, a3 = 0.f;
    for (int c = lane; c < Cc; c += 32) {
        const float qv = qrow[c];
        const float* wr = offW + c * (2 * Pp);
        a0 = fmaf(qv, wr[0], a0);
        a1 = fmaf(qv, wr[2], a1);
        a2 = fmaf(qv, wr[4], a2);
        a3 = fmaf(qv, wr[6], a3);
    }
#pragma unroll
    for (int o = 16; o > 0; o >>= 1) {
        a0 += __shfl_xor_sync(0xffffffffu, a0, o);
        a1 += __shfl_xor_sync(0xffffffffu, a1, o);
        a2 += __shfl_xor_sync(0xffffffffu, a2, o);
        a3 += __shfl_xor_sync(0xffffffffu, a3, o);
    }
    if (lane == 0) {
        g_offx[gwarp * 4 + 0] = a0 + offb[0];
        g_offx[gwarp * 4 + 1] = a1 + offb[2];
        g_offx[gwarp * 4 + 2] = a2 + offb[4];
        g_offx[gwarp * 4 + 3] = a3 + offb[6];
    }
}

// ---------------- v column sums ----------------
__global__ void __launch_bounds__(256) vspart_kernel(const float* __restrict__ v)
{
    const int idx = blockIdx.x * blockDim.x + threadIdx.x;
    const int c4 = idx % (Cc / 4);
    const int chunk = (idx / (Cc / 4)) & 127;
    const int b = idx / ((Cc / 4) * 128);
    const float4* p = (const float4*)(v + ((size_t)b * Mm + (size_t)chunk * 16) * Cc) + c4;
    float4 s = make_float4(0.f, 0.f, 0.f, 0.f);
#pragma unroll
    for (int m = 0; m < 16; m++) {
        float4 t = p[(size_t)m * (Cc / 4)];
        s.x += t.x; s.y += t.y; s.z += t.z; s.w += t.w;
    }
    ((float4*)g_vspart)[idx] = s;
}

__global__ void __launch_bounds__(256) vsred_kernel()
{
    const int idx = blockIdx.x * blockDim.x + threadIdx.x;
    const int c = idx % Cc;
    const int b = idx / Cc;
    float s = 0.f;
#pragma unroll 8
    for (int ch = 0; ch < 128; ch++) s += g_vspart[((size_t)b * 128 + ch) * Cc + c];
    g_vs[idx] = s;
}

// ---------------- pv ----------------
__global__ void __launch_bounds__(256) pv_kernel(const float* __restrict__ vW,
                                                 const float* __restrict__ projW)
{
    __shared__ float vs_s[Cc];
    __shared__ float vsum_s[Cc];
    const int b = blockIdx.x;
    for (int i = threadIdx.x; i < Cc; i += 256) vs_s[i] = g_vs[b * Cc + i];
    __syncthreads();
    for (int o = threadIdx.x; o < Cc; o += 256) {
        float s = 0.f;
        for (int c = 0; c < Cc; c++) s = fmaf(vs_s[c], vW[(size_t)c * Cc + o], s);
        vsum_s[o] = s;
    }
    __syncthreads();
    for (int o = threadIdx.x; o < Hh * Cc; o += 256) {
        const int h = o / Cc;
        const int c = o % Cc;
        float s = 0.f;
#pragma unroll
        for (int d = 0; d < Dd; d++)
            s = fmaf(vsum_s[h * Dd + d], projW[(size_t)(h * Dd + d) * Cc + c], s);
        g_pv[(size_t)b * Hh * Cc + o] = s;
    }
}

// ---------------- sampling + dot ----------------
__global__ void __launch_bounds__(256) sample_kernel()
{
    const int gwarp = (blockIdx.x * blockDim.x + threadIdx.x) >> 5;
    const int lane = threadIdx.x & 31;
    const int g = gwarp >> 11;
    const int n2 = gwarp & 2047;
    const int b = g / Hh;
    const int h = g % Hh;
    const int nq = (h * Nn + n2) / Hh;

    const float* imgg = g_imgT + (size_t)g * IMG_GRP_ELEMS;
    float accx = 0.f, accy = 0.f;
#pragma unroll
    for (int p = 0; p < Pp; p++) {
        const float offx = g_offx[((size_t)b * Nn + nq) * Pp + p];
        const float gx = offx / 2047.0f * 2.0f - 1.0f;
        const float x = (gx + 1.0f) * 0.5f * 2047.0f;
        const float x0f = floorf(x);
        const float w = x - x0f;
        const int x0 = (int)x0f;
        const int x1 = x0 + 1;
        const float w0 = (x0 >= 0 && x0 < Mm) ? (1.0f - w) : 0.0f;
        const float w1 = (x1 >= 0 && x1 < Mm) ? w : 0.0f;
        const int x0c = min(max(x0, 0), Mm - 1);
        const int x1c = min(max(x1, 0), Mm - 1);
        const float2 v0 = *(const float2*)(imgg + (size_t)x0c * Dd + 2 * lane);
        const float2 v1 = *(const float2*)(imgg + (size_t)x1c * Dd + 2 * lane);
        accx += w0 * v0.x + w1 * v1.x;
        accy += w0 * v0.y + w1 * v1.y;
    }
    const float2 qv =
        *(const float2*)(g_qp + ((size_t)b * Nn + n2) * Cc + h * Dd + 2 * lane);
    float partial = accx * qv.x + accy * qv.y;
#pragma unroll
    for (int o = 16; o > 0; o >>= 1) partial += __shfl_xor_sync(0xffffffffu, partial, o);
    if (lane == 0) g_logits[gwarp] = partial * (0.125f * 0.25f);
}

// ---------------- softmax ----------------
__global__ void __launch_bounds__(256) softmax_kernel()
{
    __shared__ float red[256];
    const int row = blockIdx.x;
    float* ptr = g_logits + (size_t)row * Nn;
    const int tid = threadIdx.x;
    float vals[8];
    float m = -1e30f;
#pragma unroll
    for (int i = 0; i < 8; i++) {
        vals[i] = ptr[tid + i * 256];
        m = fmaxf(m, vals[i]);
    }
    red[tid] = m;
    __syncthreads();
    for (int s = 128; s > 0; s >>= 1) {
        if (tid < s) red[tid] = fmaxf(red[tid], red[tid + s]);
        __syncthreads();
    }
    m = red[0];
    __syncthreads();
    float sum = 0.f;
#pragma unroll
    for (int i = 0; i < 8; i++) {
        vals[i] = expf(vals[i] - m);
        sum += vals[i];
    }
    red[tid] = sum;
    __syncthreads();
    for (int s = 128; s > 0; s >>= 1) {
        if (tid < s) red[tid] += red[tid + s];
        __syncthreads();
    }
    const float inv = 1.0f / red[0];
#pragma unroll
    for (int i = 0; i < 8; i++) ptr[tid + i * 256] = vals[i] * inv;
}

// ---------------- output ----------------
#define OUT_ROWS 32
__global__ void __launch_bounds__(256) out_kernel(const float* __restrict__ projb,
                                                  float* __restrict__ out)
{
    __shared__ float pv_s[Hh * Cc];
    __shared__ float a_s[Hh];
    const int b = blockIdx.y;
    const int n0 = blockIdx.x * OUT_ROWS;
    const int tid = threadIdx.x;
    for (int i = tid; i < Hh * Cc; i += 256) pv_s[i] = g_pv[(size_t)b * Hh * Cc + i];
    __syncthreads();
    for (int n = n0; n < n0 + OUT_ROWS; n++) {
        __syncthreads();
        if (tid < Hh) a_s[tid] = g_logits[((size_t)b * Hh + tid) * Nn + n];
        __syncthreads();
        for (int c = tid; c < Cc; c += 256) {
            float s = projb[c];
#pragma unroll
            for (int h = 0; h < Hh; h++) s = fmaf(a_s[h], pv_s[h * Cc + c], s);
            out[((size_t)b * Nn + n) * Cc + c] = s;
        }
    }
}

// ---------------- launch ----------------
extern "C" void kernel_launch(void* const* d_in, const int* in_sizes, int n_in,
                              void* d_out, int out_size)
{
    (void)in_sizes; (void)n_in; (void)out_size;
    const float* q     = (const float*)d_in[0];
    const float* k     = (const float*)d_in[1];
    const float* v     = (const float*)d_in[2];
    const float* qW    = (const float*)d_in[3];
    const float* kW    = (const float*)d_in[4];
    const float* vW    = (const float*)d_in[5];
    const float* offW  = (const float*)d_in[6];
    const float* offb  = (const float*)d_in[7];
    const float* projW = (const float*)d_in[8];
    const float* projb = (const float*)d_in[9];
    float* out = (float*)d_out;

    cudaFuncSetAttribute(tgemm_kernel<0>, cudaFuncAttributeMaxDynamicSharedMemorySize,
                         GEMM_SMEM);
    cudaFuncSetAttribute(tgemm_kernel<1>, cudaFuncAttributeMaxDynamicSharedMemorySize,
                         GEMM_SMEM);

    dim3 ggrid(Cc / 128, ROWS / 256);                       // (6, 64)
    wconv_kernel<<<Cc * Cc / 4 / 256, 256>>>(qW, 0);        // 1
    wconv_kernel<<<Cc * Cc / 4 / 256, 256>>>(kW, 1);        // 2
    aconv_kernel<<<ROWS * Cc / 4 / 256, 256>>>(k, 1);       // 3
    tgemm_kernel<1><<<ggrid, 256, GEMM_SMEM>>>(1);          // 4: kp -> imgT (profiled)
    aconv_kernel<<<ROWS * Cc / 4 / 256, 256>>>(q, 0);       // 5
    tgemm_kernel<0><<<ggrid, 256, GEMM_SMEM>>>(0);          // 6: qp
    off_kernel<<<ROWS / 8, 256>>>(q, offW, offb);
    vspart_kernel<<<(Bb * 128 * (Cc / 4)) / 256, 256>>>(v);
    vsred_kernel<<<(Bb * Cc) / 256, 256>>>();
    sample_kernel<<<(GRP * Nn) / 8, 256>>>();
    softmax_kernel<<<GRP, 256>>>();
    pv_kernel<<<Bb, 256>>>(vW, projW);
    out_kernel<<<dim3(Nn / OUT_ROWS, Bb), 256>>>(projb, out);
}